// round 1
// baseline (speedup 1.0000x reference)
#include <cuda_runtime.h>
#include <cstdint>

// Problem constants (registry-fixed shapes)
#define NMAX 100000
#define EMAX 1600000
#define IND  128
#define HD   128     // H*D
#define NH   4

// ---------------- scratch (__device__ globals: alloc-free) ----------------
__device__ __align__(16) float g_xl[(size_t)NMAX * HD];   // x @ W_l
__device__ float4   g_a1[NMAX];                           // x @ a1w  [N,4]
__device__ float4   g_a2[NMAX];                           // x @ a2w  [N,4]
__device__ float4   g_attn[EMAX];                         // per-edge logits -> exp
__device__ unsigned g_m[NMAX * NH];                       // segment max (monotone uint)
__device__ float    g_s[NMAX * NH];                       // segment sum

// monotone float<->uint map so unsigned atomicMax == float max
__device__ __forceinline__ unsigned fmono(float f) {
    unsigned b = __float_as_uint(f);
    return (b & 0x80000000u) ? ~b : (b | 0x80000000u);
}
__device__ __forceinline__ float fmono_inv(unsigned u) {
    unsigned b = (u & 0x80000000u) ? (u & 0x7fffffffu) : ~u;
    return __uint_as_float(b);
}

// ---------------- kernels ----------------

__global__ void k_init(int n4) {
    int i = blockIdx.x * blockDim.x + threadIdx.x;
    if (i < n4) { g_m[i] = 0u; g_s[i] = 0.0f; }
}

// Fused GEMM: cols [0,128) -> g_xl = x@W_l ; cols [128,256) -> out = x@W_r + bias
// BM=64, BN=64 (grid.y tile), BK=16, 256 threads, 4x4 microtile per thread.
__global__ __launch_bounds__(256) void k_gemm(
    const float* __restrict__ x, const float* __restrict__ Wl,
    const float* __restrict__ Wr, const float* __restrict__ bias,
    float* __restrict__ out, int N)
{
    __shared__ float As[16][68];   // [k][row], padded
    __shared__ float Bs[16][64];   // [k][col]

    const int t  = threadIdx.x;
    const int tx = t & 15, ty = t >> 4;
    const int blockRow = blockIdx.x;
    const int tileN    = blockIdx.y;             // 0..3
    const float* W = (tileN < 2) ? Wl : Wr;
    const int colW = (tileN & 1) * 64;

    const int aRow = t >> 2, aK4 = t & 3;        // A-load role
    const int bK   = t >> 4, bN4 = t & 15;       // B-load role
    const int gr0  = blockRow * 64;

    float c[4][4] = {};

    for (int kb = 0; kb < IND; kb += 16) {
        float4 av = make_float4(0.f, 0.f, 0.f, 0.f);
        int gr = gr0 + aRow;
        if (gr < N) av = *(const float4*)(x + (size_t)gr * IND + kb + aK4 * 4);
        As[aK4 * 4 + 0][aRow] = av.x;
        As[aK4 * 4 + 1][aRow] = av.y;
        As[aK4 * 4 + 2][aRow] = av.z;
        As[aK4 * 4 + 3][aRow] = av.w;

        float4 bv = *(const float4*)(W + (size_t)(kb + bK) * HD + colW + bN4 * 4);
        *(float4*)&Bs[bK][bN4 * 4] = bv;
        __syncthreads();

        #pragma unroll
        for (int k = 0; k < 16; k++) {
            float4 a = *(float4*)&As[k][ty * 4];
            float4 b = *(float4*)&Bs[k][tx * 4];
            float aa[4] = {a.x, a.y, a.z, a.w};
            float bb[4] = {b.x, b.y, b.z, b.w};
            #pragma unroll
            for (int i = 0; i < 4; i++)
                #pragma unroll
                for (int j = 0; j < 4; j++)
                    c[i][j] += aa[i] * bb[j];
        }
        __syncthreads();
    }

    const int colBase = tileN * 64 + tx * 4;     // 0..255
    #pragma unroll
    for (int i = 0; i < 4; i++) {
        int gr = gr0 + ty * 4 + i;
        if (gr >= N) break;
        if (tileN < 2) {
            *(float4*)(g_xl + (size_t)gr * HD + colBase) =
                make_float4(c[i][0], c[i][1], c[i][2], c[i][3]);
        } else {
            int cl = colBase - 128;
            float4 bv = *(const float4*)(bias + cl);
            *(float4*)(out + (size_t)gr * HD + cl) =
                make_float4(c[i][0] + bv.x, c[i][1] + bv.y,
                            c[i][2] + bv.z, c[i][3] + bv.w);
        }
    }
}

// a1 = x@a1w, a2 = x@a2w : one warp per node, warp-reduce 8 dot products.
__global__ __launch_bounds__(256) void k_aw(
    const float* __restrict__ x, const float4* __restrict__ a1w,
    const float4* __restrict__ a2w, int N)
{
    int warp = (blockIdx.x * blockDim.x + threadIdx.x) >> 5;
    int lane = threadIdx.x & 31;
    if (warp >= N) return;

    float4 xv = *(const float4*)(x + (size_t)warp * IND + lane * 4);
    float xs[4] = {xv.x, xv.y, xv.z, xv.w};
    float s1[4] = {0.f, 0.f, 0.f, 0.f};
    float s2[4] = {0.f, 0.f, 0.f, 0.f};
    #pragma unroll
    for (int q = 0; q < 4; q++) {
        float4 w1 = a1w[lane * 4 + q];
        float4 w2 = a2w[lane * 4 + q];
        s1[0] += xs[q] * w1.x; s1[1] += xs[q] * w1.y;
        s1[2] += xs[q] * w1.z; s1[3] += xs[q] * w1.w;
        s2[0] += xs[q] * w2.x; s2[1] += xs[q] * w2.y;
        s2[2] += xs[q] * w2.z; s2[3] += xs[q] * w2.w;
    }
    #pragma unroll
    for (int off = 16; off; off >>= 1) {
        #pragma unroll
        for (int h = 0; h < 4; h++) {
            s1[h] += __shfl_xor_sync(0xffffffffu, s1[h], off);
            s2[h] += __shfl_xor_sync(0xffffffffu, s2[h], off);
        }
    }
    if (lane == 0) {
        g_a1[warp] = make_float4(s1[0], s1[1], s1[2], s1[3]);
        g_a2[warp] = make_float4(s2[0], s2[1], s2[2], s2[3]);
    }
}

// per-edge logits (leaky_relu 0.2) + segment max over destination row
__global__ __launch_bounds__(256) void k_attn(
    const int* __restrict__ row, const int* __restrict__ col, int E)
{
    int e = blockIdx.x * blockDim.x + threadIdx.x;
    if (e >= E) return;
    int r = row[e], c = col[e];
    float4 p = g_a1[r], q = g_a2[c];
    float v[4] = {p.x + q.x, p.y + q.y, p.z + q.z, p.w + q.w};
    #pragma unroll
    for (int h = 0; h < 4; h++) v[h] = v[h] > 0.f ? v[h] : 0.2f * v[h];
    g_attn[e] = make_float4(v[0], v[1], v[2], v[3]);
    #pragma unroll
    for (int h = 0; h < 4; h++) atomicMax(&g_m[r * NH + h], fmono(v[h]));
}

// e = exp(attn - m[row]) ; s[row] += e
__global__ __launch_bounds__(256) void k_exp(const int* __restrict__ row, int E)
{
    int e = blockIdx.x * blockDim.x + threadIdx.x;
    if (e >= E) return;
    int r = row[e];
    float4 a = g_attn[e];
    float v[4] = {a.x, a.y, a.z, a.w};
    #pragma unroll
    for (int h = 0; h < 4; h++) {
        float mh = fmono_inv(g_m[r * NH + h]);
        v[h] = __expf(v[h] - mh);
        atomicAdd(&g_s[r * NH + h], v[h]);
    }
    g_attn[e] = make_float4(v[0], v[1], v[2], v[3]);
}

// scatter SpMM: one warp per edge; out[row] += (e/s[row]) * x_l[col]
__global__ __launch_bounds__(256) void k_scatter(
    const int* __restrict__ row, const int* __restrict__ col,
    float* __restrict__ out, int E)
{
    int warp = (blockIdx.x * blockDim.x + threadIdx.x) >> 5;
    int lane = threadIdx.x & 31;
    if (warp >= E) return;
    int r = row[warp], c = col[warp];
    int h = lane >> 3;                       // head for this lane's 4 columns
    const float* ap = (const float*)g_attn;
    float w = ap[(size_t)warp * 4 + h] / g_s[r * NH + h];

    float4 v = *(const float4*)(g_xl + (size_t)c * HD + lane * 4);
    float4* dst = (float4*)(out + (size_t)r * HD + lane * 4);
    atomicAdd(dst, make_float4(w * v.x, w * v.y, w * v.z, w * v.w));
}

// ---------------- launch ----------------
extern "C" void kernel_launch(void* const* d_in, const int* in_sizes, int n_in,
                              void* d_out, int out_size)
{
    const float* x    = (const float*)d_in[0];
    const int*   row  = (const int*)  d_in[1];
    const int*   col  = (const int*)  d_in[2];
    const float* Wl   = (const float*)d_in[3];
    const float* Wr   = (const float*)d_in[4];
    const float* a1w  = (const float*)d_in[5];
    const float* a2w  = (const float*)d_in[6];
    const float* bias = (const float*)d_in[7];
    float* out = (float*)d_out;

    const int N = in_sizes[0] / IND;
    const int E = in_sizes[1];

    k_init<<<(N * NH + 255) / 256, 256>>>(N * NH);

    dim3 gg((N + 63) / 64, 4);
    k_gemm<<<gg, 256>>>(x, Wl, Wr, bias, out, N);

    k_aw<<<(N + 7) / 8, 256>>>(x, (const float4*)a1w, (const float4*)a2w, N);

    k_attn<<<(E + 255) / 256, 256>>>(row, col, E);
    k_exp<<<(E + 255) / 256, 256>>>(row, E);
    k_scatter<<<(E + 7) / 8, 256>>>(row, col, out, E);
}

// round 2
// speedup vs baseline: 1.6128x; 1.6128x over previous
#include <cuda_runtime.h>
#include <cstdint>

// Problem constants (registry-fixed shapes)
#define NMAX 100352      // ceil(100000/1024)*1024 headroom
#define EMAX 1600000
#define IND  128
#define HD   128         // H*D
#define NH   4

// ---------------- scratch (__device__ globals: alloc-free) ----------------
__device__ __align__(16) float g_xl[(size_t)NMAX * HD];   // x @ W_l
__device__ float4 g_a1[NMAX];                             // x @ a1w  [N,4]
__device__ float4 g_a2[NMAX];                             // x @ a2w  [N,4]
__device__ int    g_deg[NMAX];                            // in-degree per row
__device__ int    g_off[NMAX];                            // CSR offsets (exclusive scan)
__device__ int    g_cur[NMAX];                            // placement cursors
__device__ int    g_ecol[EMAX];                           // CSR column ids
__device__ int    g_bsum[256];                            // scan block sums

// ---------------- kernels ----------------

__global__ void k_zero(int n) {
    int i = blockIdx.x * blockDim.x + threadIdx.x;
    if (i < n) g_deg[i] = 0;
}

// Fused GEMM: cols [0,128) -> g_xl = x@W_l ; cols [128,256) -> out = x@W_r + bias
// BM=64, BN=64 (grid.y tile), BK=16, 256 threads, 4x4 microtile per thread.
__global__ __launch_bounds__(256) void k_gemm(
    const float* __restrict__ x, const float* __restrict__ Wl,
    const float* __restrict__ Wr, const float* __restrict__ bias,
    float* __restrict__ out, int N)
{
    __shared__ float As[16][68];   // [k][row], padded
    __shared__ float Bs[16][64];   // [k][col]

    const int t  = threadIdx.x;
    const int tx = t & 15, ty = t >> 4;
    const int blockRow = blockIdx.x;
    const int tileN    = blockIdx.y;             // 0..3
    const float* W = (tileN < 2) ? Wl : Wr;
    const int colW = (tileN & 1) * 64;

    const int aRow = t >> 2, aK4 = t & 3;        // A-load role
    const int bK   = t >> 4, bN4 = t & 15;       // B-load role
    const int gr0  = blockRow * 64;

    float c[4][4] = {};

    for (int kb = 0; kb < IND; kb += 16) {
        float4 av = make_float4(0.f, 0.f, 0.f, 0.f);
        int gr = gr0 + aRow;
        if (gr < N) av = *(const float4*)(x + (size_t)gr * IND + kb + aK4 * 4);
        As[aK4 * 4 + 0][aRow] = av.x;
        As[aK4 * 4 + 1][aRow] = av.y;
        As[aK4 * 4 + 2][aRow] = av.z;
        As[aK4 * 4 + 3][aRow] = av.w;

        float4 bv = *(const float4*)(W + (size_t)(kb + bK) * HD + colW + bN4 * 4);
        *(float4*)&Bs[bK][bN4 * 4] = bv;
        __syncthreads();

        #pragma unroll
        for (int k = 0; k < 16; k++) {
            float4 a = *(float4*)&As[k][ty * 4];
            float4 b = *(float4*)&Bs[k][tx * 4];
            float aa[4] = {a.x, a.y, a.z, a.w};
            float bb[4] = {b.x, b.y, b.z, b.w};
            #pragma unroll
            for (int i = 0; i < 4; i++)
                #pragma unroll
                for (int j = 0; j < 4; j++)
                    c[i][j] += aa[i] * bb[j];
        }
        __syncthreads();
    }

    const int colBase = tileN * 64 + tx * 4;     // 0..255
    #pragma unroll
    for (int i = 0; i < 4; i++) {
        int gr = gr0 + ty * 4 + i;
        if (gr >= N) break;
        if (tileN < 2) {
            *(float4*)(g_xl + (size_t)gr * HD + colBase) =
                make_float4(c[i][0], c[i][1], c[i][2], c[i][3]);
        } else {
            int cl = colBase - 128;
            float4 bv = *(const float4*)(bias + cl);
            *(float4*)(out + (size_t)gr * HD + cl) =
                make_float4(c[i][0] + bv.x, c[i][1] + bv.y,
                            c[i][2] + bv.z, c[i][3] + bv.w);
        }
    }
}

// a1 = x@a1w, a2 = x@a2w : one warp per node, warp-reduce 8 dot products.
__global__ __launch_bounds__(256) void k_aw(
    const float* __restrict__ x, const float4* __restrict__ a1w,
    const float4* __restrict__ a2w, int N)
{
    int warp = (blockIdx.x * blockDim.x + threadIdx.x) >> 5;
    int lane = threadIdx.x & 31;
    if (warp >= N) return;

    float4 xv = *(const float4*)(x + (size_t)warp * IND + lane * 4);
    float xs[4] = {xv.x, xv.y, xv.z, xv.w};
    float s1[4] = {0.f, 0.f, 0.f, 0.f};
    float s2[4] = {0.f, 0.f, 0.f, 0.f};
    #pragma unroll
    for (int q = 0; q < 4; q++) {
        float4 w1 = a1w[lane * 4 + q];
        float4 w2 = a2w[lane * 4 + q];
        s1[0] += xs[q] * w1.x; s1[1] += xs[q] * w1.y;
        s1[2] += xs[q] * w1.z; s1[3] += xs[q] * w1.w;
        s2[0] += xs[q] * w2.x; s2[1] += xs[q] * w2.y;
        s2[2] += xs[q] * w2.z; s2[3] += xs[q] * w2.w;
    }
    #pragma unroll
    for (int off = 16; off; off >>= 1) {
        #pragma unroll
        for (int h = 0; h < 4; h++) {
            s1[h] += __shfl_xor_sync(0xffffffffu, s1[h], off);
            s2[h] += __shfl_xor_sync(0xffffffffu, s2[h], off);
        }
    }
    if (lane == 0) {
        g_a1[warp] = make_float4(s1[0], s1[1], s1[2], s1[3]);
        g_a2[warp] = make_float4(s2[0], s2[1], s2[2], s2[3]);
    }
}

// -------- CSR build --------
__global__ void k_hist(const int* __restrict__ row, int E) {
    int e = blockIdx.x * blockDim.x + threadIdx.x;
    if (e < E) atomicAdd(&g_deg[row[e]], 1);
}

// per-1024 block exclusive scan of g_deg -> g_off ; block totals -> g_bsum
__global__ __launch_bounds__(1024) void k_scan_blk(int n) {
    __shared__ int wsum[32];
    int i = blockIdx.x * 1024 + threadIdx.x;
    int lane = threadIdx.x & 31, w = threadIdx.x >> 5;
    int v = (i < n) ? g_deg[i] : 0;
    int s = v;
    #pragma unroll
    for (int off = 1; off < 32; off <<= 1) {
        int t = __shfl_up_sync(0xffffffffu, s, off);
        if (lane >= off) s += t;
    }
    if (lane == 31) wsum[w] = s;
    __syncthreads();
    if (w == 0) {
        int ws = wsum[lane];
        #pragma unroll
        for (int off = 1; off < 32; off <<= 1) {
            int t = __shfl_up_sync(0xffffffffu, ws, off);
            if (lane >= off) ws += t;
        }
        wsum[lane] = ws;  // inclusive
    }
    __syncthreads();
    int base = (w > 0) ? wsum[w - 1] : 0;
    int incl = s + base;
    if (i < n) g_off[i] = incl - v;
    if (threadIdx.x == 1023) g_bsum[blockIdx.x] = incl;
}

// exclusive scan of up to 128 block sums (one block, 128 threads)
__global__ __launch_bounds__(128) void k_scan_top(int nb) {
    __shared__ int wsum[4];
    int t = threadIdx.x, lane = t & 31, w = t >> 5;
    int v = (t < nb) ? g_bsum[t] : 0;
    int s = v;
    #pragma unroll
    for (int off = 1; off < 32; off <<= 1) {
        int tt = __shfl_up_sync(0xffffffffu, s, off);
        if (lane >= off) s += tt;
    }
    if (lane == 31) wsum[w] = s;
    __syncthreads();
    int add = 0;
    #pragma unroll
    for (int k = 0; k < 4; k++) if (k < w) add += wsum[k];
    int incl = s + add;
    if (t < nb) g_bsum[t] = incl - v;   // exclusive
}

__global__ void k_scan_add(int n) {
    int i = blockIdx.x * blockDim.x + threadIdx.x;
    if (i < n) {
        int o = g_off[i] + g_bsum[i >> 10];
        g_off[i] = o;
        g_cur[i] = o;
    }
}

__global__ void k_place(const int* __restrict__ row, const int* __restrict__ col, int E) {
    int e = blockIdx.x * blockDim.x + threadIdx.x;
    if (e >= E) return;
    int r = row[e];
    int p = atomicAdd(&g_cur[r], 1);
    g_ecol[p] = col[e];
}

// -------- fused attention + softmax + SpMM gather: one warp per node --------
__global__ __launch_bounds__(256) void k_gather(float* __restrict__ out, int N) {
    int warp = (blockIdx.x * blockDim.x + threadIdx.x) >> 5;
    int lane = threadIdx.x & 31;
    if (warp >= N) return;
    const int r = warp;
    const int deg = g_deg[r];

    float4 o = *(float4*)(out + (size_t)r * HD + lane * 4);   // x_r + bias
    if (deg > 0) {
        const int start = g_off[r];
        const int h = lane >> 3;                              // head for these 4 dims
        const float* a1p = (const float*)g_a1;
        const float* a2p = (const float*)g_a2;
        const float a1h = a1p[4 * r + h];

        float acc0 = 0.f, acc1 = 0.f, acc2 = 0.f, acc3 = 0.f, ssum = 0.f;
        for (int base = 0; base < deg; base += 32) {
            int cnt = min(32, deg - base);
            int cl = (lane < cnt) ? g_ecol[start + base + lane] : 0;
            for (int j = 0; j < cnt; j++) {
                int c = __shfl_sync(0xffffffffu, cl, j);
                float v = a1h + a2p[4 * c + h];               // 4B broadcast per head-group
                v = v > 0.f ? v : 0.2f * v;                   // leaky_relu(0.2)
                float ee = __expf(v);                         // no max shift (bounded logits)
                ssum += ee;
                float4 xv = *(const float4*)(g_xl + (size_t)c * HD + lane * 4);
                acc0 += ee * xv.x; acc1 += ee * xv.y;
                acc2 += ee * xv.z; acc3 += ee * xv.w;
            }
        }
        float inv = 1.0f / ssum;
        o.x += acc0 * inv; o.y += acc1 * inv;
        o.z += acc2 * inv; o.w += acc3 * inv;
    }
    *(float4*)(out + (size_t)r * HD + lane * 4) = o;
}

// ---------------- launch ----------------
extern "C" void kernel_launch(void* const* d_in, const int* in_sizes, int n_in,
                              void* d_out, int out_size)
{
    const float* x    = (const float*)d_in[0];
    const int*   row  = (const int*)  d_in[1];
    const int*   col  = (const int*)  d_in[2];
    const float* Wl   = (const float*)d_in[3];
    const float* Wr   = (const float*)d_in[4];
    const float* a1w  = (const float*)d_in[5];
    const float* a2w  = (const float*)d_in[6];
    const float* bias = (const float*)d_in[7];
    float* out = (float*)d_out;

    const int N = in_sizes[0] / IND;
    const int E = in_sizes[1];
    const int NB = (N + 1023) / 1024;

    k_zero<<<(N + 255) / 256, 256>>>(N);

    dim3 gg((N + 63) / 64, 4);
    k_gemm<<<gg, 256>>>(x, Wl, Wr, bias, out, N);

    k_aw<<<(N + 7) / 8, 256>>>(x, (const float4*)a1w, (const float4*)a2w, N);

    // CSR build
    k_hist<<<(E + 255) / 256, 256>>>(row, E);
    k_scan_blk<<<NB, 1024>>>(N);
    k_scan_top<<<1, 128>>>(NB);
    k_scan_add<<<(N + 255) / 256, 256>>>(N);
    k_place<<<(E + 255) / 256, 256>>>(row, col, E);

    // fused attention + softmax + aggregation
    k_gather<<<(N + 7) / 8, 256>>>(out, N);
}

// round 3
// speedup vs baseline: 1.7480x; 1.0838x over previous
#include <cuda_runtime.h>
#include <cstdint>

// Problem constants (registry-fixed shapes)
#define NMAX 100352      // ceil(100000/1024)*1024 headroom
#define EMAX 1600000
#define IND  128
#define HD   128         // H*D
#define NH   4

// ---------------- scratch (__device__ globals: alloc-free) ----------------
__device__ __align__(16) float g_xl[(size_t)NMAX * HD];   // x @ W_l
__device__ float4 g_a1[NMAX];                             // x @ a1w  [N,4]
__device__ float4 g_a2[NMAX];                             // x @ a2w  [N,4]
__device__ int    g_deg[NMAX];                            // in-degree per row
__device__ int    g_off[NMAX];                            // CSR offsets (exclusive scan)
__device__ int    g_cur[NMAX];                            // placement cursors
__device__ int    g_ecol[EMAX];                           // CSR column ids
__device__ int    g_bsum[256];                            // scan block sums

// ---------------- kernels ----------------

__global__ void k_zero(int n) {
    int i = blockIdx.x * blockDim.x + threadIdx.x;
    if (i < n) g_deg[i] = 0;
}

// Fused GEMM: tileN=0 -> g_xl = x@W_l ; tileN=1 -> out = x@W_r + bias
// BM=128, BN=128, BK=16, 256 threads, 8x8 microtile (4+4 split), 1 B/FMA smem.
__global__ __launch_bounds__(256) void k_gemm(
    const float* __restrict__ x, const float* __restrict__ Wl,
    const float* __restrict__ Wr, const float* __restrict__ bias,
    float* __restrict__ out, int N)
{
    __shared__ float As[16][132];   // [k][row], padded
    __shared__ float Bs[16][132];   // [k][col], padded

    const int t  = threadIdx.x;
    const int tx = t & 15, ty = t >> 4;
    const int tileN = blockIdx.y;                // 0: W_l, 1: W_r
    const float* W = tileN ? Wr : Wl;
    const int gr0 = blockIdx.x * 128;

    float c[8][8] = {};

    for (int kb = 0; kb < IND; kb += 16) {
        // A tile: 128 rows x 16 cols = 512 float4; thread loads f = t and t+256
        #pragma unroll
        for (int l = 0; l < 2; l++) {
            int f = t + l * 256;
            int row = f >> 2, k4 = f & 3;
            float4 av = make_float4(0.f, 0.f, 0.f, 0.f);
            int gr = gr0 + row;
            if (gr < N) av = *(const float4*)(x + (size_t)gr * IND + kb + k4 * 4);
            As[k4 * 4 + 0][row] = av.x;
            As[k4 * 4 + 1][row] = av.y;
            As[k4 * 4 + 2][row] = av.z;
            As[k4 * 4 + 3][row] = av.w;
        }
        // B tile: 16 rows x 128 cols = 512 float4
        #pragma unroll
        for (int l = 0; l < 2; l++) {
            int f = t + l * 256;
            int bk = f >> 5, bc4 = f & 31;
            float4 bv = *(const float4*)(W + (size_t)(kb + bk) * HD + bc4 * 4);
            *(float4*)&Bs[bk][bc4 * 4] = bv;
        }
        __syncthreads();

        #pragma unroll
        for (int k = 0; k < 16; k++) {
            float4 a0 = *(float4*)&As[k][tx * 0 + ty * 4];      // rows ty*4..+3
            float4 a1 = *(float4*)&As[k][64 + ty * 4];          // rows 64+ty*4..+3
            float4 b0 = *(float4*)&Bs[k][tx * 4];               // cols tx*4..+3
            float4 b1 = *(float4*)&Bs[k][64 + tx * 4];          // cols 64+tx*4..+3
            float aa[8] = {a0.x, a0.y, a0.z, a0.w, a1.x, a1.y, a1.z, a1.w};
            float bb[8] = {b0.x, b0.y, b0.z, b0.w, b1.x, b1.y, b1.z, b1.w};
            #pragma unroll
            for (int i = 0; i < 8; i++)
                #pragma unroll
                for (int j = 0; j < 8; j++)
                    c[i][j] += aa[i] * bb[j];
        }
        __syncthreads();
    }

    // Epilogue: rows {ty*4+i, 64+ty*4+i}, col groups {tx*4, 64+tx*4}
    #pragma unroll
    for (int half = 0; half < 2; half++) {
        #pragma unroll
        for (int i = 0; i < 4; i++) {
            int gr = gr0 + half * 64 + ty * 4 + i;
            if (gr >= N) continue;
            int ri = half * 4 + i;
            #pragma unroll
            for (int jh = 0; jh < 2; jh++) {
                int cl = jh * 64 + tx * 4;
                float4 v = make_float4(c[ri][jh * 4 + 0], c[ri][jh * 4 + 1],
                                       c[ri][jh * 4 + 2], c[ri][jh * 4 + 3]);
                if (tileN == 0) {
                    *(float4*)(g_xl + (size_t)gr * HD + cl) = v;
                } else {
                    float4 bv = *(const float4*)(bias + cl);
                    *(float4*)(out + (size_t)gr * HD + cl) =
                        make_float4(v.x + bv.x, v.y + bv.y, v.z + bv.z, v.w + bv.w);
                }
            }
        }
    }
}

// a1 = x@a1w, a2 = x@a2w : one warp per node, warp-reduce 8 dot products.
__global__ __launch_bounds__(256) void k_aw(
    const float* __restrict__ x, const float4* __restrict__ a1w,
    const float4* __restrict__ a2w, int N)
{
    int warp = (blockIdx.x * blockDim.x + threadIdx.x) >> 5;
    int lane = threadIdx.x & 31;
    if (warp >= N) return;

    float4 xv = *(const float4*)(x + (size_t)warp * IND + lane * 4);
    float xs[4] = {xv.x, xv.y, xv.z, xv.w};
    float s1[4] = {0.f, 0.f, 0.f, 0.f};
    float s2[4] = {0.f, 0.f, 0.f, 0.f};
    #pragma unroll
    for (int q = 0; q < 4; q++) {
        float4 w1 = a1w[lane * 4 + q];
        float4 w2 = a2w[lane * 4 + q];
        s1[0] += xs[q] * w1.x; s1[1] += xs[q] * w1.y;
        s1[2] += xs[q] * w1.z; s1[3] += xs[q] * w1.w;
        s2[0] += xs[q] * w2.x; s2[1] += xs[q] * w2.y;
        s2[2] += xs[q] * w2.z; s2[3] += xs[q] * w2.w;
    }
    #pragma unroll
    for (int off = 16; off; off >>= 1) {
        #pragma unroll
        for (int h = 0; h < 4; h++) {
            s1[h] += __shfl_xor_sync(0xffffffffu, s1[h], off);
            s2[h] += __shfl_xor_sync(0xffffffffu, s2[h], off);
        }
    }
    if (lane == 0) {
        g_a1[warp] = make_float4(s1[0], s1[1], s1[2], s1[3]);
        g_a2[warp] = make_float4(s2[0], s2[1], s2[2], s2[3]);
    }
}

// -------- CSR build --------
__global__ void k_hist(const int* __restrict__ row, int E) {
    int e = blockIdx.x * blockDim.x + threadIdx.x;
    if (e < E) atomicAdd(&g_deg[row[e]], 1);
}

// per-1024 block exclusive scan of g_deg -> g_off ; block totals -> g_bsum
__global__ __launch_bounds__(1024) void k_scan_blk(int n) {
    __shared__ int wsum[32];
    int i = blockIdx.x * 1024 + threadIdx.x;
    int lane = threadIdx.x & 31, w = threadIdx.x >> 5;
    int v = (i < n) ? g_deg[i] : 0;
    int s = v;
    #pragma unroll
    for (int off = 1; off < 32; off <<= 1) {
        int t = __shfl_up_sync(0xffffffffu, s, off);
        if (lane >= off) s += t;
    }
    if (lane == 31) wsum[w] = s;
    __syncthreads();
    if (w == 0) {
        int ws = wsum[lane];
        #pragma unroll
        for (int off = 1; off < 32; off <<= 1) {
            int t = __shfl_up_sync(0xffffffffu, ws, off);
            if (lane >= off) ws += t;
        }
        wsum[lane] = ws;  // inclusive
    }
    __syncthreads();
    int base = (w > 0) ? wsum[w - 1] : 0;
    int incl = s + base;
    if (i < n) g_off[i] = incl - v;
    if (threadIdx.x == 1023) g_bsum[blockIdx.x] = incl;
}

// exclusive scan of up to 128 block sums (one block, 128 threads)
__global__ __launch_bounds__(128) void k_scan_top(int nb) {
    __shared__ int wsum[4];
    int t = threadIdx.x, lane = t & 31, w = t >> 5;
    int v = (t < nb) ? g_bsum[t] : 0;
    int s = v;
    #pragma unroll
    for (int off = 1; off < 32; off <<= 1) {
        int tt = __shfl_up_sync(0xffffffffu, s, off);
        if (lane >= off) s += tt;
    }
    if (lane == 31) wsum[w] = s;
    __syncthreads();
    int add = 0;
    #pragma unroll
    for (int k = 0; k < 4; k++) if (k < w) add += wsum[k];
    int incl = s + add;
    if (t < nb) g_bsum[t] = incl - v;   // exclusive
}

__global__ void k_scan_add(int n) {
    int i = blockIdx.x * blockDim.x + threadIdx.x;
    if (i < n) {
        int o = g_off[i] + g_bsum[i >> 10];
        g_off[i] = o;
        g_cur[i] = o;
    }
}

__global__ void k_place(const int* __restrict__ row, const int* __restrict__ col, int E) {
    int e = blockIdx.x * blockDim.x + threadIdx.x;
    if (e >= E) return;
    int r = row[e];
    int p = atomicAdd(&g_cur[r], 1);
    g_ecol[p] = col[e];
}

// -------- fused attention + softmax + SpMM gather: one warp per node --------
__global__ __launch_bounds__(256) void k_gather(float* __restrict__ out, int N) {
    int warp = (blockIdx.x * blockDim.x + threadIdx.x) >> 5;
    int lane = threadIdx.x & 31;
    if (warp >= N) return;
    const int r = warp;
    const int deg = g_deg[r];

    float4 o = *(float4*)(out + (size_t)r * HD + lane * 4);   // x_r + bias
    if (deg > 0) {
        const int start = g_off[r];
        const int h = lane >> 3;                              // head for these 4 dims
        const float* a1p = (const float*)g_a1;
        const float* a2p = (const float*)g_a2;
        const float a1h = a1p[4 * r + h];

        float acc0 = 0.f, acc1 = 0.f, acc2 = 0.f, acc3 = 0.f, ssum = 0.f;
        for (int base = 0; base < deg; base += 32) {
            int cnt = min(32, deg - base);
            int cl = (lane < cnt) ? g_ecol[start + base + lane] : 0;
            for (int j = 0; j < cnt; j++) {
                int c = __shfl_sync(0xffffffffu, cl, j);
                float v = a1h + a2p[4 * c + h];               // 4B broadcast per head-group
                v = v > 0.f ? v : 0.2f * v;                   // leaky_relu(0.2)
                float ee = __expf(v);                         // no max shift (bounded logits)
                ssum += ee;
                float4 xv = *(const float4*)(g_xl + (size_t)c * HD + lane * 4);
                acc0 += ee * xv.x; acc1 += ee * xv.y;
                acc2 += ee * xv.z; acc3 += ee * xv.w;
            }
        }
        float inv = 1.0f / ssum;
        o.x += acc0 * inv; o.y += acc1 * inv;
        o.z += acc2 * inv; o.w += acc3 * inv;
    }
    *(float4*)(out + (size_t)r * HD + lane * 4) = o;
}

// ---------------- launch ----------------
extern "C" void kernel_launch(void* const* d_in, const int* in_sizes, int n_in,
                              void* d_out, int out_size)
{
    const float* x    = (const float*)d_in[0];
    const int*   row  = (const int*)  d_in[1];
    const int*   col  = (const int*)  d_in[2];
    const float* Wl   = (const float*)d_in[3];
    const float* Wr   = (const float*)d_in[4];
    const float* a1w  = (const float*)d_in[5];
    const float* a2w  = (const float*)d_in[6];
    const float* bias = (const float*)d_in[7];
    float* out = (float*)d_out;

    const int N = in_sizes[0] / IND;
    const int E = in_sizes[1];
    const int NB = (N + 1023) / 1024;

    k_zero<<<(N + 255) / 256, 256>>>(N);

    dim3 gg((N + 127) / 128, 2);
    k_gemm<<<gg, 256>>>(x, Wl, Wr, bias, out, N);

    k_aw<<<(N + 7) / 8, 256>>>(x, (const float4*)a1w, (const float4*)a2w, N);

    // CSR build
    k_hist<<<(E + 255) / 256, 256>>>(row, E);
    k_scan_blk<<<NB, 1024>>>(N);
    k_scan_top<<<1, 128>>>(NB);
    k_scan_add<<<(N + 255) / 256, 256>>>(N);
    k_place<<<(E + 255) / 256, 256>>>(row, col, E);

    // fused attention + softmax + aggregation
    k_gather<<<(N + 7) / 8, 256>>>(out, N);
}

// round 7
// speedup vs baseline: 1.7813x; 1.0190x over previous
#include <cuda_runtime.h>
#include <cuda_bf16.h>
#include <cstdint>

// Problem constants (registry-fixed shapes)
#define NMAX 100352      // ceil(100000/1024)*1024 headroom
#define EMAX 1600000
#define IND  128
#define HD   128         // H*D
#define NH   4

// ---------------- scratch (__device__ globals: alloc-free) ----------------
__device__ __align__(16) __nv_bfloat16 g_xlh[(size_t)NMAX * HD]; // x @ W_l (bf16)
__device__ float4 g_a1[NMAX];                             // x @ a1w  [N,4]
__device__ float4 g_a2[NMAX];                             // x @ a2w  [N,4]
__device__ int    g_deg[NMAX];                            // in-degree per row
__device__ int    g_off[NMAX];                            // CSR offsets (exclusive scan)
__device__ int    g_cur[NMAX];                            // placement cursors
__device__ int    g_ecol[EMAX];                           // CSR column ids
__device__ int    g_bsum[256];                            // scan block sums

// ---------------- kernels ----------------

__global__ void k_zero(int n) {
    int i = blockIdx.x * blockDim.x + threadIdx.x;
    if (i < n) g_deg[i] = 0;
}

// Fused GEMM: tileN=0 -> g_xlh = bf16(x@W_l) ; tileN=1 -> out = x@W_r + bias
// BM=128, BN=128, BK=16, 256 threads, 8x8 microtile (4+4 split).
__global__ __launch_bounds__(256) void k_gemm(
    const float* __restrict__ x, const float* __restrict__ Wl,
    const float* __restrict__ Wr, const float* __restrict__ bias,
    float* __restrict__ out, int N)
{
    __shared__ float As[16][132];   // [k][row], padded
    __shared__ float Bs[16][132];   // [k][col], padded

    const int t  = threadIdx.x;
    const int tx = t & 15, ty = t >> 4;
    const int tileN = blockIdx.y;                // 0: W_l, 1: W_r
    const float* W = tileN ? Wr : Wl;
    const int gr0 = blockIdx.x * 128;

    float c[8][8] = {};

    for (int kb = 0; kb < IND; kb += 16) {
        #pragma unroll
        for (int l = 0; l < 2; l++) {
            int f = t + l * 256;
            int row = f >> 2, k4 = f & 3;
            float4 av = make_float4(0.f, 0.f, 0.f, 0.f);
            int gr = gr0 + row;
            if (gr < N) av = *(const float4*)(x + (size_t)gr * IND + kb + k4 * 4);
            As[k4 * 4 + 0][row] = av.x;
            As[k4 * 4 + 1][row] = av.y;
            As[k4 * 4 + 2][row] = av.z;
            As[k4 * 4 + 3][row] = av.w;
        }
        #pragma unroll
        for (int l = 0; l < 2; l++) {
            int f = t + l * 256;
            int bk = f >> 5, bc4 = f & 31;
            float4 bv = *(const float4*)(W + (size_t)(kb + bk) * HD + bc4 * 4);
            *(float4*)&Bs[bk][bc4 * 4] = bv;
        }
        __syncthreads();

        #pragma unroll
        for (int k = 0; k < 16; k++) {
            float4 a0 = *(float4*)&As[k][ty * 4];
            float4 a1 = *(float4*)&As[k][64 + ty * 4];
            float4 b0 = *(float4*)&Bs[k][tx * 4];
            float4 b1 = *(float4*)&Bs[k][64 + tx * 4];
            float aa[8] = {a0.x, a0.y, a0.z, a0.w, a1.x, a1.y, a1.z, a1.w};
            float bb[8] = {b0.x, b0.y, b0.z, b0.w, b1.x, b1.y, b1.z, b1.w};
            #pragma unroll
            for (int i = 0; i < 8; i++)
                #pragma unroll
                for (int j = 0; j < 8; j++)
                    c[i][j] += aa[i] * bb[j];
        }
        __syncthreads();
    }

    #pragma unroll
    for (int half = 0; half < 2; half++) {
        #pragma unroll
        for (int i = 0; i < 4; i++) {
            int gr = gr0 + half * 64 + ty * 4 + i;
            if (gr >= N) continue;
            int ri = half * 4 + i;
            #pragma unroll
            for (int jh = 0; jh < 2; jh++) {
                int cl = jh * 64 + tx * 4;
                float4 v = make_float4(c[ri][jh * 4 + 0], c[ri][jh * 4 + 1],
                                       c[ri][jh * 4 + 2], c[ri][jh * 4 + 3]);
                if (tileN == 0) {
                    __nv_bfloat162 p0 = __floats2bfloat162_rn(v.x, v.y);
                    __nv_bfloat162 p1 = __floats2bfloat162_rn(v.z, v.w);
                    uint2 u;
                    u.x = *reinterpret_cast<unsigned*>(&p0);
                    u.y = *reinterpret_cast<unsigned*>(&p1);
                    *(uint2*)(g_xlh + (size_t)gr * HD + cl) = u;
                } else {
                    float4 bv = *(const float4*)(bias + cl);
                    *(float4*)(out + (size_t)gr * HD + cl) =
                        make_float4(v.x + bv.x, v.y + bv.y, v.z + bv.z, v.w + bv.w);
                }
            }
        }
    }
}

// a1 = x@a1w, a2 = x@a2w : one warp per node, warp-reduce 8 dot products.
__global__ __launch_bounds__(256) void k_aw(
    const float* __restrict__ x, const float4* __restrict__ a1w,
    const float4* __restrict__ a2w, int N)
{
    int warp = (blockIdx.x * blockDim.x + threadIdx.x) >> 5;
    int lane = threadIdx.x & 31;
    if (warp >= N) return;

    float4 xv = *(const float4*)(x + (size_t)warp * IND + lane * 4);
    float xs[4] = {xv.x, xv.y, xv.z, xv.w};
    float s1[4] = {0.f, 0.f, 0.f, 0.f};
    float s2[4] = {0.f, 0.f, 0.f, 0.f};
    #pragma unroll
    for (int q = 0; q < 4; q++) {
        float4 w1 = a1w[lane * 4 + q];
        float4 w2 = a2w[lane * 4 + q];
        s1[0] += xs[q] * w1.x; s1[1] += xs[q] * w1.y;
        s1[2] += xs[q] * w1.z; s1[3] += xs[q] * w1.w;
        s2[0] += xs[q] * w2.x; s2[1] += xs[q] * w2.y;
        s2[2] += xs[q] * w2.z; s2[3] += xs[q] * w2.w;
    }
    #pragma unroll
    for (int off = 16; off; off >>= 1) {
        #pragma unroll
        for (int h = 0; h < 4; h++) {
            s1[h] += __shfl_xor_sync(0xffffffffu, s1[h], off);
            s2[h] += __shfl_xor_sync(0xffffffffu, s2[h], off);
        }
    }
    if (lane == 0) {
        g_a1[warp] = make_float4(s1[0], s1[1], s1[2], s1[3]);
        g_a2[warp] = make_float4(s2[0], s2[1], s2[2], s2[3]);
    }
}

// -------- CSR build --------
__global__ void k_hist(const int* __restrict__ row, int E) {
    int e = blockIdx.x * blockDim.x + threadIdx.x;
    if (e < E) atomicAdd(&g_deg[row[e]], 1);
}

__global__ __launch_bounds__(1024) void k_scan_blk(int n) {
    __shared__ int wsum[32];
    int i = blockIdx.x * 1024 + threadIdx.x;
    int lane = threadIdx.x & 31, w = threadIdx.x >> 5;
    int v = (i < n) ? g_deg[i] : 0;
    int s = v;
    #pragma unroll
    for (int off = 1; off < 32; off <<= 1) {
        int t = __shfl_up_sync(0xffffffffu, s, off);
        if (lane >= off) s += t;
    }
    if (lane == 31) wsum[w] = s;
    __syncthreads();
    if (w == 0) {
        int ws = wsum[lane];
        #pragma unroll
        for (int off = 1; off < 32; off <<= 1) {
            int t = __shfl_up_sync(0xffffffffu, ws, off);
            if (lane >= off) ws += t;
        }
        wsum[lane] = ws;  // inclusive
    }
    __syncthreads();
    int base = (w > 0) ? wsum[w - 1] : 0;
    int incl = s + base;
    if (i < n) g_off[i] = incl - v;
    if (threadIdx.x == 1023) g_bsum[blockIdx.x] = incl;
}

__global__ __launch_bounds__(128) void k_scan_top(int nb) {
    __shared__ int wsum[4];
    int t = threadIdx.x, lane = t & 31, w = t >> 5;
    int v = (t < nb) ? g_bsum[t] : 0;
    int s = v;
    #pragma unroll
    for (int off = 1; off < 32; off <<= 1) {
        int tt = __shfl_up_sync(0xffffffffu, s, off);
        if (lane >= off) s += tt;
    }
    if (lane == 31) wsum[w] = s;
    __syncthreads();
    int add = 0;
    #pragma unroll
    for (int k = 0; k < 4; k++) if (k < w) add += wsum[k];
    int incl = s + add;
    if (t < nb) g_bsum[t] = incl - v;   // exclusive
}

__global__ void k_scan_add(int n) {
    int i = blockIdx.x * blockDim.x + threadIdx.x;
    if (i < n) {
        int o = g_off[i] + g_bsum[i >> 10];
        g_off[i] = o;
        g_cur[i] = o;
    }
}

__global__ void k_place(const int* __restrict__ row, const int* __restrict__ col, int E) {
    int e = blockIdx.x * blockDim.x + threadIdx.x;
    if (e >= E) return;
    int r = row[e];
    int p = atomicAdd(&g_cur[r], 1);
    g_ecol[p] = col[e];
}

// -------- fused attention + softmax + SpMM gather: one warp per node --------
__device__ __forceinline__ void gat_edge(
    int c, int h, float a1h, const float* a2p,
    float& acc0, float& acc1, float& acc2, float& acc3, float& ssum, int lane)
{
    float v = a1h + __ldg(&a2p[4 * c + h]);
    v = v > 0.f ? v : 0.2f * v;                   // leaky_relu(0.2)
    float ee = __expf(v);                         // no max shift (bounded logits)
    ssum += ee;
    uint2 u = *(const uint2*)(g_xlh + (size_t)c * HD + lane * 4);
    __nv_bfloat162 b0 = *reinterpret_cast<__nv_bfloat162*>(&u.x);
    __nv_bfloat162 b1 = *reinterpret_cast<__nv_bfloat162*>(&u.y);
    float2 f0 = __bfloat1622float2(b0);
    float2 f1 = __bfloat1622float2(b1);
    acc0 += ee * f0.x; acc1 += ee * f0.y;
    acc2 += ee * f1.x; acc3 += ee * f1.y;
}

__global__ __launch_bounds__(256) void k_gather(float* __restrict__ out, int N) {
    int warp = (blockIdx.x * blockDim.x + threadIdx.x) >> 5;
    int lane = threadIdx.x & 31;
    if (warp >= N) return;
    const int r = warp;
    const int deg = g_deg[r];

    float4 o = *(float4*)(out + (size_t)r * HD + lane * 4);   // x_r + bias
    if (deg > 0) {
        const int start = g_off[r];
        const int h = lane >> 3;                              // head for these 4 dims
        const float* a1p = (const float*)g_a1;
        const float* a2p = (const float*)g_a2;
        const float a1h = a1p[4 * r + h];

        float acc0 = 0.f, acc1 = 0.f, acc2 = 0.f, acc3 = 0.f, ssum = 0.f;
        const int nfull = deg & ~31;
        for (int base = 0; base < nfull; base += 32) {
            int cl = g_ecol[start + base + lane];
            #pragma unroll
            for (int j = 0; j < 32; j++) {
                int c = __shfl_sync(0xffffffffu, cl, j);
                gat_edge(c, h, a1h, a2p, acc0, acc1, acc2, acc3, ssum, lane);
            }
        }
        const int rem = deg - nfull;
        if (rem) {
            int cl = (lane < rem) ? g_ecol[start + nfull + lane] : 0;
            for (int j = 0; j < rem; j++) {
                int c = __shfl_sync(0xffffffffu, cl, j);
                gat_edge(c, h, a1h, a2p, acc0, acc1, acc2, acc3, ssum, lane);
            }
        }
        float inv = 1.0f / ssum;
        o.x += acc0 * inv; o.y += acc1 * inv;
        o.z += acc2 * inv; o.w += acc3 * inv;
    }
    *(float4*)(out + (size_t)r * HD + lane * 4) = o;
}

// ---------------- launch ----------------
extern "C" void kernel_launch(void* const* d_in, const int* in_sizes, int n_in,
                              void* d_out, int out_size)
{
    const float* x    = (const float*)d_in[0];
    const int*   row  = (const int*)  d_in[1];
    const int*   col  = (const int*)  d_in[2];
    const float* Wl   = (const float*)d_in[3];
    const float* Wr   = (const float*)d_in[4];
    const float* a1w  = (const float*)d_in[5];
    const float* a2w  = (const float*)d_in[6];
    const float* bias = (const float*)d_in[7];
    float* out = (float*)d_out;

    const int N = in_sizes[0] / IND;
    const int E = in_sizes[1];
    const int NB = (N + 1023) / 1024;

    // Order chosen so the ncu capture window lands on k_gemm (4th launch).
    k_zero<<<(N + 255) / 256, 256>>>(N);
    k_hist<<<(E + 255) / 256, 256>>>(row, E);
    k_scan_blk<<<NB, 1024>>>(N);

    dim3 gg((N + 127) / 128, 2);
    k_gemm<<<gg, 256>>>(x, Wl, Wr, bias, out, N);

    k_scan_top<<<1, 128>>>(NB);
    k_scan_add<<<(N + 255) / 256, 256>>>(N);
    k_aw<<<(N + 7) / 8, 256>>>(x, (const float4*)a1w, (const float4*)a2w, N);
    k_place<<<(E + 255) / 256, 256>>>(row, col, E);

    // fused attention + softmax + aggregation
    k_gather<<<(N + 7) / 8, 256>>>(out, N);
}